// round 4
// baseline (speedup 1.0000x reference)
#include <cuda_runtime.h>
#include <cstdint>
#include <math.h>

// ---------------------------------------------------------------------------
// LOUPE sampler: prob-mask -> rescale -> rejection-sample binarize (JAX
// threefry, PARTITIONABLE path) -> broadcast multiply over kspace.
// Output layout: [masked_kspace (256*2*320*320 f32)] [mask_full (256*1*320*320 f32)]
// ---------------------------------------------------------------------------

#define SLOPE 5.0f
#define LN 320

__device__ float d_mask[LN];

// --- threefry2x32, 20 rounds ---
__device__ __forceinline__ uint32_t rotl32(uint32_t v, int d) {
    return (v << d) | (v >> (32 - d));
}

__device__ __forceinline__ void threefry2x32(uint32_t k0, uint32_t k1,
                                             uint32_t c0, uint32_t c1,
                                             uint32_t& o0, uint32_t& o1) {
    uint32_t k2 = k0 ^ k1 ^ 0x1BD11BDAu;
    uint32_t x0 = c0 + k0;
    uint32_t x1 = c1 + k1;
#define TF_ROUND(r) { x0 += x1; x1 = rotl32(x1, (r)); x1 ^= x0; }
    TF_ROUND(13) TF_ROUND(15) TF_ROUND(26) TF_ROUND(6)
    x0 += k1; x1 += k2 + 1u;
    TF_ROUND(17) TF_ROUND(29) TF_ROUND(16) TF_ROUND(24)
    x0 += k2; x1 += k0 + 2u;
    TF_ROUND(13) TF_ROUND(15) TF_ROUND(26) TF_ROUND(6)
    x0 += k0; x1 += k1 + 3u;
    TF_ROUND(17) TF_ROUND(29) TF_ROUND(16) TF_ROUND(24)
    x0 += k1; x1 += k2 + 4u;
    TF_ROUND(13) TF_ROUND(15) TF_ROUND(26) TF_ROUND(6)
    x0 += k2; x1 += k0 + 5u;
#undef TF_ROUND
    o0 = x0; o1 = x1;
}

// JAX float32 uniform from 32 random bits: (bits>>9)|0x3f800000 bitcast - 1.0
__device__ __forceinline__ float bits_to_uniform(uint32_t b) {
    return __uint_as_float((b >> 9) | 0x3f800000u) - 1.0f;
}

// ---------------------------------------------------------------------------
// Kernel A: compute the 320-line binary mask. One block, 320 threads.
// Uses JAX's *partitionable* threefry:
//   split(key):  keys[j] = threefry(key, 0, j)          (j = 0 -> new key, 1 -> sub)
//   bits(key,i): x0 ^ x1 of threefry(key, 0, i)         (64-bit iota: hi=0, lo=i)
// ---------------------------------------------------------------------------
__global__ void __launch_bounds__(LN) compute_mask_kernel(
    const float* __restrict__ logits, const float* __restrict__ sparsity_p) {
    __shared__ float xs[LN];
    __shared__ float sh_xbar, sh_xm;
    __shared__ uint32_t key0, key1, sub0, sub1;

    const int tid = threadIdx.x;
    const float sparsity = *sparsity_p;

    // prob mask: sigmoid(SLOPE * logits)
    float s = 1.0f / (1.0f + expf(-SLOPE * logits[tid]));
    xs[tid] = s;
    __syncthreads();

    // mean (thread-0 serial; acceptance is count==80 which tolerates ulp noise)
    if (tid == 0) {
        float acc = 0.0f;
        for (int i = 0; i < LN; i++) acc += xs[i];
        sh_xbar = acc / (float)LN;
    }
    __syncthreads();
    const float xbar = sh_xbar;

    // RescaleProbMap
    const float r = sparsity / xbar;
    const float beta = (1.0f - sparsity) / (1.0f - xbar);
    float x = (r <= 1.0f) ? (s * r) : (1.0f - (1.0f - s) * beta);
    xs[tid] = x;
    __syncthreads();

    if (tid == 0) {
        float acc = 0.0f;
        for (int i = 0; i < LN; i++) acc += xs[i];
        sh_xm = acc / (float)LN;
        key0 = 0u;    // jax.random.key(42) -> raw data (0, 42)
        key1 = 42u;
    }
    __syncthreads();
    const float xm = sh_xm;

    // rejection sampling: redraw uniforms until mean(x > prob) ~= mean(x)
    bool res = false;
    for (int iter = 0; iter < 100000; ++iter) {
        // key, sub = jax.random.split(key)  [fold-like / partitionable]
        if (tid == 0) {
            uint32_t nk0, nk1, ns0, ns1;
            threefry2x32(key0, key1, 0u, 0u, nk0, nk1);
            threefry2x32(key0, key1, 0u, 1u, ns0, ns1);
            key0 = nk0; key1 = nk1;
            sub0 = ns0; sub1 = ns1;
        }
        __syncthreads();

        // prob[i] = uniform from bits = x0 ^ x1 of threefry(sub, hi=0, lo=i)
        uint32_t u, v;
        threefry2x32(sub0, sub1, 0u, (uint32_t)tid, u, v);
        float p = bits_to_uniform(u ^ v);

        res = x > p;
        int cnt = __syncthreads_count(res ? 1 : 0);
        float m = (float)cnt / (float)LN;
        if (fabsf(m - xm) <= 1e-3f + 1e-5f * fabsf(xm)) break;
    }

    // preselect outermost lines
    float v = res ? 1.0f : 0.0f;
    if (tid == 0 || tid == LN - 1) v = 1.0f;
    d_mask[tid] = v;
}

// ---------------------------------------------------------------------------
// Kernel B: out[0:n4m) = kspace * mask[h] ; out[n4m:n4tot) = mask[h] broadcast
// float4 granularity; W=320 -> 80 float4 per row.
// ---------------------------------------------------------------------------
__global__ void __launch_bounds__(256) apply_mask_kernel(
    const float4* __restrict__ ksp, float4* __restrict__ out,
    int n4m, int n4tot) {
    int idx = blockIdx.x * blockDim.x + threadIdx.x;
    if (idx >= n4tot) return;
    if (idx < n4m) {
        int row = idx / 80;            // row of 320 floats
        float m = d_mask[row % LN];    // h index
        float4 a = ksp[idx];
        a.x *= m; a.y *= m; a.z *= m; a.w *= m;
        out[idx] = a;
    } else {
        int row = (idx - n4m) / 80;
        float m = d_mask[row % LN];
        out[idx] = make_float4(m, m, m, m);
    }
}

extern "C" void kernel_launch(void* const* d_in, const int* in_sizes, int n_in,
                              void* d_out, int out_size) {
    const float* kspace   = (const float*)d_in[0];  // (256,2,320,320)
    const float* sparsity = (const float*)d_in[1];  // scalar
    const float* logits   = (const float*)d_in[2];  // (320,)

    compute_mask_kernel<<<1, LN>>>(logits, sparsity);

    int n4m   = in_sizes[0] / 4;   // masked_kspace float4 count
    int n4tot = out_size / 4;      // masked + mask_full
    int threads = 256;
    int blocks = (n4tot + threads - 1) / threads;
    apply_mask_kernel<<<blocks, threads>>>(
        (const float4*)kspace, (float4*)d_out, n4m, n4tot);
}

// round 6
// speedup vs baseline: 1.0318x; 1.0318x over previous
#include <cuda_runtime.h>
#include <cstdint>
#include <math.h>

// ---------------------------------------------------------------------------
// LOUPE sampler, parallelized rejection sampling:
//   A1: probs + rescale + means + threefry split-chain (data-independent)
//   A2: 32 candidate draws evaluated in parallel across 64 blocks
//   A3: select first accepted candidate (sequential fallback if none of 32)
//   B : broadcast multiply (pure bandwidth, streaming hints)
// Output: [masked_kspace 256*2*320*320 f32][mask_full 256*1*320*320 f32]
// ---------------------------------------------------------------------------

#define SLOPE 5.0f
#define LN 320
#define NPROBE 32

__device__ float    d_mask[LN];
__device__ float    d_xs[LN];
__device__ float    d_xm;
__device__ uint2    d_subs[NPROBE];
__device__ uint2    d_chain_key;
__device__ int      d_cnt[NPROBE];
__device__ uint32_t d_words[NPROBE][10];

// --- threefry2x32, 20 rounds (JAX) ---
__device__ __forceinline__ uint32_t rotl32(uint32_t v, int d) {
    return (v << d) | (v >> (32 - d));
}

__device__ __forceinline__ void threefry2x32(uint32_t k0, uint32_t k1,
                                             uint32_t c0, uint32_t c1,
                                             uint32_t& o0, uint32_t& o1) {
    uint32_t k2 = k0 ^ k1 ^ 0x1BD11BDAu;
    uint32_t x0 = c0 + k0;
    uint32_t x1 = c1 + k1;
#define TF_ROUND(r) { x0 += x1; x1 = rotl32(x1, (r)); x1 ^= x0; }
    TF_ROUND(13) TF_ROUND(15) TF_ROUND(26) TF_ROUND(6)
    x0 += k1; x1 += k2 + 1u;
    TF_ROUND(17) TF_ROUND(29) TF_ROUND(16) TF_ROUND(24)
    x0 += k2; x1 += k0 + 2u;
    TF_ROUND(13) TF_ROUND(15) TF_ROUND(26) TF_ROUND(6)
    x0 += k0; x1 += k1 + 3u;
    TF_ROUND(17) TF_ROUND(29) TF_ROUND(16) TF_ROUND(24)
    x0 += k1; x1 += k2 + 4u;
    TF_ROUND(13) TF_ROUND(15) TF_ROUND(26) TF_ROUND(6)
    x0 += k2; x1 += k0 + 5u;
#undef TF_ROUND
    o0 = x0; o1 = x1;
}

__device__ __forceinline__ float bits_to_uniform(uint32_t b) {
    return __uint_as_float((b >> 9) | 0x3f800000u) - 1.0f;
}

// ---------------------------------------------------------------------------
// A1: 352 threads. Threads <320: sigmoid + rescale + (thread 0) means.
//     Thread 320 concurrently builds the split chain key_0..key_31.
//     After sync, 32 lanes derive sub_i = threefry(key_i, 0, 1) in parallel.
// JAX partitionable threefry:
//   split(key):  new = threefry(key,0,0), sub = threefry(key,0,1)
//   bits(key,i): x0 ^ x1 of threefry(key, 0, i)
// ---------------------------------------------------------------------------
__global__ void __launch_bounds__(352) prep_kernel(
    const float* __restrict__ logits, const float* __restrict__ sparsity_p) {
    __shared__ float xs[LN];
    __shared__ float sh_xbar;
    __shared__ uint2 keych[NPROBE];

    const int tid = threadIdx.x;
    float s = 0.0f;

    if (tid < LN) {
        s = 1.0f / (1.0f + expf(-SLOPE * logits[tid]));
        xs[tid] = s;
    }
    if (tid == 320) {
        // data-independent split chain
        uint32_t k0 = 0u, k1 = 42u;   // jax.random.key(42)
        for (int i = 0; i < NPROBE; i++) {
            keych[i] = make_uint2(k0, k1);
            uint32_t n0, n1;
            threefry2x32(k0, k1, 0u, 0u, n0, n1);
            k0 = n0; k1 = n1;
        }
        d_chain_key = make_uint2(k0, k1);   // state after NPROBE splits (fallback)
    }
    __syncthreads();

    if (tid == 0) {
        float a = 0.0f;
        for (int i = 0; i < LN; i++) a += xs[i];
        sh_xbar = a / (float)LN;
    }
    __syncthreads();

    if (tid < LN) {
        const float sparsity = *sparsity_p;
        const float xbar = sh_xbar;
        const float r = sparsity / xbar;
        const float beta = (1.0f - sparsity) / (1.0f - xbar);
        float x = (r <= 1.0f) ? (s * r) : (1.0f - (1.0f - s) * beta);
        xs[tid] = x;
        d_xs[tid] = x;
    }
    __syncthreads();

    if (tid == 0) {
        float a = 0.0f;
        for (int i = 0; i < LN; i++) a += xs[i];
        d_xm = a / (float)LN;
    }
    if (tid < NPROBE) {
        uint2 kk = keych[tid];
        uint32_t u, v;
        threefry2x32(kk.x, kk.y, 0u, 1u, u, v);   // sub key for iteration tid
        d_subs[tid] = make_uint2(u, v);
        d_cnt[tid] = 0;
    }
}

// ---------------------------------------------------------------------------
// A2: 64 blocks x 160 threads. Block (it = b>>1, half = b&1) draws lines
//     [half*160, half*160+160) of candidate iteration `it`.
// ---------------------------------------------------------------------------
__global__ void __launch_bounds__(160) probe_kernel() {
    const int it = blockIdx.x >> 1;
    const int half = blockIdx.x & 1;
    const int tid = threadIdx.x;
    const int j = half * 160 + tid;

    const uint2 sub = d_subs[it];
    uint32_t u, v;
    threefry2x32(sub.x, sub.y, 0u, (uint32_t)j, u, v);
    const float p = bits_to_uniform(u ^ v);
    const int pred = d_xs[j] > p;

    const uint32_t b = __ballot_sync(0xffffffffu, pred);
    if ((tid & 31) == 0) d_words[it][half * 5 + (tid >> 5)] = b;

    const int c = __syncthreads_count(pred);
    if (tid == 0) atomicAdd(&d_cnt[it], c);
}

// ---------------------------------------------------------------------------
// A3: 1 block x 320. Select first accepted candidate; fallback continues the
//     sequential rejection loop from d_chain_key (correct for any key).
// ---------------------------------------------------------------------------
__global__ void __launch_bounds__(LN) finalize_kernel() {
    __shared__ int sh_sel;
    __shared__ uint32_t key0, key1, sub0, sub1;

    const int tid = threadIdx.x;
    const float xm = d_xm;
    const float tol = 1e-3f + 1e-5f * fabsf(xm);

    if (tid == 0) {
        int sel = -1;
        for (int i = 0; i < NPROBE; i++) {
            float m = (float)d_cnt[i] / (float)LN;
            if (fabsf(m - xm) <= tol) { sel = i; break; }
        }
        sh_sel = sel;
        if (sel < 0) { key0 = d_chain_key.x; key1 = d_chain_key.y; }
    }
    __syncthreads();
    const int sel = sh_sel;

    float vout;
    if (sel >= 0) {
        uint32_t w = d_words[sel][tid >> 5];
        vout = ((w >> (tid & 31)) & 1u) ? 1.0f : 0.0f;
    } else {
        // fallback: continue the sequential chain (deterministic, rare)
        const float x = d_xs[tid];
        bool res = false;
        for (int iter = 0; iter < 100000; ++iter) {
            if (tid == 0) {
                uint32_t nk0, nk1, ns0, ns1;
                threefry2x32(key0, key1, 0u, 0u, nk0, nk1);
                threefry2x32(key0, key1, 0u, 1u, ns0, ns1);
                key0 = nk0; key1 = nk1;
                sub0 = ns0; sub1 = ns1;
            }
            __syncthreads();
            uint32_t u, v;
            threefry2x32(sub0, sub1, 0u, (uint32_t)tid, u, v);
            float p = bits_to_uniform(u ^ v);
            res = x > p;
            int cnt = __syncthreads_count(res ? 1 : 0);
            float m = (float)cnt / (float)LN;
            if (fabsf(m - xm) <= tol) break;
        }
        vout = res ? 1.0f : 0.0f;
    }

    if (tid == 0 || tid == LN - 1) vout = 1.0f;
    d_mask[tid] = vout;
}

// ---------------------------------------------------------------------------
// B: out[0:n4m) = kspace * mask[h] ; out[n4m:n4tot) = mask[h] broadcast.
//    Streaming loads/stores (no reuse on the big streams).
// ---------------------------------------------------------------------------
__global__ void __launch_bounds__(256) apply_mask_kernel(
    const float4* __restrict__ ksp, float4* __restrict__ out,
    int n4m, int n4tot) {
    int idx = blockIdx.x * blockDim.x + threadIdx.x;
    if (idx >= n4tot) return;
    if (idx < n4m) {
        int row = idx / 80;            // row of 320 floats (W=320 -> 80 float4)
        float m = d_mask[row % LN];
        float4 a = __ldcs(&ksp[idx]);
        a.x *= m; a.y *= m; a.z *= m; a.w *= m;
        __stcs(&out[idx], a);
    } else {
        int row = (idx - n4m) / 80;
        float m = d_mask[row % LN];
        __stcs(&out[idx], make_float4(m, m, m, m));
    }
}

extern "C" void kernel_launch(void* const* d_in, const int* in_sizes, int n_in,
                              void* d_out, int out_size) {
    const float* kspace   = (const float*)d_in[0];  // (256,2,320,320)
    const float* sparsity = (const float*)d_in[1];  // scalar
    const float* logits   = (const float*)d_in[2];  // (320,)

    prep_kernel<<<1, 352>>>(logits, sparsity);
    probe_kernel<<<2 * NPROBE, 160>>>();
    finalize_kernel<<<1, LN>>>();

    int n4m   = in_sizes[0] / 4;
    int n4tot = out_size / 4;
    int threads = 256;
    int blocks = (n4tot + threads - 1) / threads;
    apply_mask_kernel<<<blocks, threads>>>(
        (const float4*)kspace, (float4*)d_out, n4m, n4tot);
}